// round 9
// baseline (speedup 1.0000x reference)
#include <cuda_runtime.h>
#include <cuda_fp16.h>
#include <mma.h>
#include <math.h>

using namespace nvcuda;

#define N_NODES   40000
#define N_EDGES   640000
#define FDIM      128
#define N_GRAPHS  64
#define N_CLASSES 10

#define SCAN_B    1024
#define SCAN_NB   ((N_NODES + SCAN_B - 1) / SCAN_B)   // 40

// ---------------- scratch (device globals; no allocations) ------------------
__device__ __align__(16) __half g_X16[N_NODES * FDIM];
__device__ __align__(16) __half g_A16[N_NODES * FDIM];
__device__ __align__(16) __half g_B16[N_NODES * FDIM];
__device__ __align__(16) __half g_Whi[3 * FDIM * FDIM];
__device__ __align__(16) __half g_Wlo[3 * FDIM * FDIM];
__device__ int    g_indeg[N_NODES];
__device__ float  g_dis[N_NODES];
__device__ int    g_off[N_NODES];
__device__ int    g_cursor[N_NODES];
__device__ int    g_bagg[SCAN_NB];
__device__ volatile int g_bflag[SCAN_NB];
__device__ int2   g_srcwt[N_EDGES];
__device__ float  g_sums[N_GRAPHS * FDIM];
__device__ float  g_cnts[N_GRAPHS];

// ---------------- conversions ------------------------------------------------
__global__ void x_to_h_kernel(const float* __restrict__ x) {
    int idx = blockIdx.x * blockDim.x + threadIdx.x;
    if (idx >= N_NODES * 32) return;
    float4 v = ((const float4*)x)[idx];
    __half2 h0 = __floats2half2_rn(v.x, v.y);
    __half2 h1 = __floats2half2_rn(v.z, v.w);
    uint2 u; u.x = *(unsigned*)&h0; u.y = *(unsigned*)&h1;
    ((uint2*)g_X16)[idx] = u;
}

__global__ void w_split_kernel(const float* __restrict__ W1,
                               const float* __restrict__ W2,
                               const float* __restrict__ W3) {
    int idx = blockIdx.x * blockDim.x + threadIdx.x;
    if (idx >= FDIM * FDIM) return;
    const float* Ws[3] = {W1, W2, W3};
#pragma unroll
    for (int l = 0; l < 3; l++) {
        float w = Ws[l][idx];
        __half hi = __float2half_rn(w);
        float lo = w - __half2float(hi);
        g_Whi[l * FDIM * FDIM + idx] = hi;
        g_Wlo[l * FDIM * FDIM + idx] = __float2half_rn(lo);
    }
}

// ---------------- init: zero indeg + pool sums + lookback flags --------------
__global__ void init_kernel() {
    int i = blockIdx.x * blockDim.x + threadIdx.x;
    if (i < N_NODES) g_indeg[i] = 0;
    if (i < N_GRAPHS * FDIM) g_sums[i] = 0.f;
    if (i < N_GRAPHS) g_cnts[i] = 0.f;
    if (i < SCAN_NB) { g_bflag[i] = 0; g_bagg[i] = 0; }
}

__global__ void deg_count_kernel(const int* __restrict__ col) {
    int e = blockIdx.x * blockDim.x + threadIdx.x;
    if (e < N_EDGES) atomicAdd(&g_indeg[col[e]], 1);
}

// ---------------- fused scan: local scan + decoupled lookback ----------------
__global__ void scan_fused_kernel() {
    __shared__ int s[SCAN_B];
    __shared__ int sh_prefix;
    int tid = threadIdx.x;
    int b   = blockIdx.x;
    int gid = b * SCAN_B + tid;

    int v = (gid < N_NODES) ? g_indeg[gid] : 0;
    if (gid < N_NODES) g_dis[gid] = rsqrtf((float)(v + 1));
    s[tid] = v;
    __syncthreads();
#pragma unroll
    for (int off = 1; off < SCAN_B; off <<= 1) {
        int t = 0;
        if (tid >= off) t = s[tid - off];
        __syncthreads();
        if (tid >= off) s[tid] += t;
        __syncthreads();
    }

    if (tid == 0) {
        g_bagg[b] = s[SCAN_B - 1];
        __threadfence();
        g_bflag[b] = 1;
        int run = 0;
        for (int i = 0; i < b; i++) {
            while (g_bflag[i] == 0) { }
            run += g_bagg[i];
        }
        sh_prefix = run;
    }
    __syncthreads();

    if (gid < N_NODES) {
        int o = s[tid] - v + sh_prefix;
        g_off[gid] = o;
        g_cursor[gid] = o;
    }
}

// ---------------- CSR fill ---------------------------------------------------
__global__ void fill_kernel(const int* __restrict__ row,
                            const int* __restrict__ col) {
    int e = blockIdx.x * blockDim.x + threadIdx.x;
    if (e >= N_EDGES) return;
    int r = row[e];
    int c = col[e];
    int p = atomicAdd(&g_cursor[c], 1);
    float w = g_dis[r] * g_dis[c];
    g_srcwt[p] = make_int2(r, __float_as_int(w));
}

// ---------------- wmma GEMM: Y16 = X16 @ (Whi + Wlo) ------------------------
#define GEMM_BM  64
#define LDP      136
#define GEMM_SMEM_BYTES ((2 * 128 * LDP + GEMM_BM * LDP) * 2)
__global__ __launch_bounds__(256, 2)
void gemm_wmma_kernel(const __half* __restrict__ X,
                      const __half* __restrict__ Whi,
                      const __half* __restrict__ Wlo,
                      __half* __restrict__ Y) {
    extern __shared__ __half smh[];
    __half* Wh = smh;
    __half* Wl = smh + 128 * LDP;
    __half* Xs = smh + 2 * 128 * LDP;

    int tid  = threadIdx.x;
    int row0 = blockIdx.x * GEMM_BM;

    const float4* Wh4 = (const float4*)Whi;
    const float4* Wl4 = (const float4*)Wlo;
#pragma unroll
    for (int i = 0; i < 8; i++) {
        int idx = tid + 256 * i;
        int r = idx >> 4, c8 = idx & 15;
        *(float4*)(Wh + r * LDP + c8 * 8) = Wh4[idx];
        *(float4*)(Wl + r * LDP + c8 * 8) = Wl4[idx];
    }
    const float4* X4 = (const float4*)(X + (size_t)row0 * FDIM);
#pragma unroll
    for (int i = 0; i < 4; i++) {
        int idx = tid + 256 * i;
        int r = idx >> 4, c8 = idx & 15;
        *(float4*)(Xs + r * LDP + c8 * 8) = X4[idx];
    }
    __syncthreads();

    int warp = tid >> 5;
    int wr = warp >> 1;
    int wc = warp & 1;

    wmma::fragment<wmma::matrix_a, 16, 16, 16, __half, wmma::row_major> a_frag;
    wmma::fragment<wmma::matrix_b, 16, 16, 16, __half, wmma::row_major> bh, bl;
    wmma::fragment<wmma::accumulator, 16, 16, 16, float> acc[4];
#pragma unroll
    for (int j = 0; j < 4; j++) wmma::fill_fragment(acc[j], 0.0f);

#pragma unroll
    for (int kk = 0; kk < 8; kk++) {
        wmma::load_matrix_sync(a_frag, Xs + (wr * 16) * LDP + kk * 16, LDP);
#pragma unroll
        for (int j = 0; j < 4; j++) {
            int coff = wc * 64 + j * 16;
            wmma::load_matrix_sync(bh, Wh + (kk * 16) * LDP + coff, LDP);
            wmma::mma_sync(acc[j], a_frag, bh, acc[j]);
            wmma::load_matrix_sync(bl, Wl + (kk * 16) * LDP + coff, LDP);
            wmma::mma_sync(acc[j], a_frag, bl, acc[j]);
        }
    }

#pragma unroll
    for (int j = 0; j < 4; j++) {
        wmma::fragment<wmma::accumulator, 16, 16, 16, __half> hfrag;
#pragma unroll
        for (int t = 0; t < hfrag.num_elements; t++)
            hfrag.x[t] = __float2half_rn(acc[j].x[t]);
        wmma::store_matrix_sync(
            Y + (size_t)(row0 + wr * 16) * FDIM + wc * 64 + j * 16,
            hfrag, FDIM, wmma::mem_row_major);
    }
}

// ---------------- half8 (uint4) -> 8 floats ----------------------------------
__device__ __forceinline__ void h8_to_f8(uint4 u, float* f) {
    float2 a = __half22float2(*(__half2*)&u.x);
    float2 b = __half22float2(*(__half2*)&u.y);
    float2 c = __half22float2(*(__half2*)&u.z);
    float2 d = __half22float2(*(__half2*)&u.w);
    f[0] = a.x; f[1] = a.y; f[2] = b.x; f[3] = b.y;
    f[4] = c.x; f[5] = c.y; f[6] = d.x; f[7] = d.y;
}

// ---------------- CSR gather: HALF-WARP per node ------------------------------
// 16 lanes x uint4 (16B) = 256B row in ONE LDG.128 issue per half-warp.
// Each warp serves 2 nodes -> warp-LDG count halves vs warp-per-node.
template <int POOL>
__global__ void gather_kernel(const float* __restrict__ bias,
                              const int* __restrict__ batch) {
    int warp = blockIdx.x * (blockDim.x >> 5) + (threadIdx.x >> 5);
    int lane = threadIdx.x & 31;
    int halfsel = (lane >> 4);             // 0 or 1
    int node = warp * 2 + halfsel;
    if (node >= N_NODES) return;
    int hl = lane & 15;                    // lane within half
    int hbase = lane & 16;                 // shfl source base for my half

    const uint4* B4 = (const uint4*)g_B16;

    int beg = g_off[node];
    int deg = g_indeg[node];

    float dn = g_dis[node];
    float sl = dn * dn;

    float acc[8];
    {
        float sv[8];
        h8_to_f8(B4[(size_t)node * 16 + hl], sv);
#pragma unroll
        for (int k = 0; k < 8; k++) acc[k] = sv[k] * sl;
    }

    for (int base = 0; base < deg; base += 16) {
        int rem = deg - base; if (rem > 16) rem = 16;
        int2 my = make_int2(0, 0);
        if (hl < rem) my = __ldg(&g_srcwt[beg + base + hl]);

        int j = 0;
        for (; j + 4 <= rem; j += 4) {
            int s0 = __shfl_sync(0xffffffffu, my.x, hbase | (j + 0));
            int s1 = __shfl_sync(0xffffffffu, my.x, hbase | (j + 1));
            int s2 = __shfl_sync(0xffffffffu, my.x, hbase | (j + 2));
            int s3 = __shfl_sync(0xffffffffu, my.x, hbase | (j + 3));
            float w0 = __int_as_float(__shfl_sync(0xffffffffu, my.y, hbase | (j + 0)));
            float w1 = __int_as_float(__shfl_sync(0xffffffffu, my.y, hbase | (j + 1)));
            float w2 = __int_as_float(__shfl_sync(0xffffffffu, my.y, hbase | (j + 2)));
            float w3 = __int_as_float(__shfl_sync(0xffffffffu, my.y, hbase | (j + 3)));
            uint4 u0 = __ldg(&B4[(size_t)s0 * 16 + hl]);
            uint4 u1 = __ldg(&B4[(size_t)s1 * 16 + hl]);
            uint4 u2 = __ldg(&B4[(size_t)s2 * 16 + hl]);
            uint4 u3 = __ldg(&B4[(size_t)s3 * 16 + hl]);
            float v[8];
            h8_to_f8(u0, v);
#pragma unroll
            for (int k = 0; k < 8; k++) acc[k] = fmaf(w0, v[k], acc[k]);
            h8_to_f8(u1, v);
#pragma unroll
            for (int k = 0; k < 8; k++) acc[k] = fmaf(w1, v[k], acc[k]);
            h8_to_f8(u2, v);
#pragma unroll
            for (int k = 0; k < 8; k++) acc[k] = fmaf(w2, v[k], acc[k]);
            h8_to_f8(u3, v);
#pragma unroll
            for (int k = 0; k < 8; k++) acc[k] = fmaf(w3, v[k], acc[k]);
        }
        for (; j < rem; j++) {
            int   sj = __shfl_sync(0xffffffffu, my.x, hbase | j);
            float wj = __int_as_float(__shfl_sync(0xffffffffu, my.y, hbase | j));
            float v[8];
            h8_to_f8(__ldg(&B4[(size_t)sj * 16 + hl]), v);
#pragma unroll
            for (int k = 0; k < 8; k++) acc[k] = fmaf(wj, v[k], acc[k]);
        }
    }

    float4 bv0 = __ldg(&((const float4*)bias)[hl * 2]);
    float4 bv1 = __ldg(&((const float4*)bias)[hl * 2 + 1]);
    acc[0] = fmaxf(acc[0] + bv0.x, 0.f);
    acc[1] = fmaxf(acc[1] + bv0.y, 0.f);
    acc[2] = fmaxf(acc[2] + bv0.z, 0.f);
    acc[3] = fmaxf(acc[3] + bv0.w, 0.f);
    acc[4] = fmaxf(acc[4] + bv1.x, 0.f);
    acc[5] = fmaxf(acc[5] + bv1.y, 0.f);
    acc[6] = fmaxf(acc[6] + bv1.z, 0.f);
    acc[7] = fmaxf(acc[7] + bv1.w, 0.f);

    if (POOL) {
        int g = __ldg(&batch[node]);
        float* dst = g_sums + (size_t)g * FDIM + hl * 8;
        asm volatile("red.global.add.v4.f32 [%0], {%1, %2, %3, %4};"
                     :: "l"(dst), "f"(acc[0]), "f"(acc[1]), "f"(acc[2]), "f"(acc[3])
                     : "memory");
        asm volatile("red.global.add.v4.f32 [%0], {%1, %2, %3, %4};"
                     :: "l"(dst + 4), "f"(acc[4]), "f"(acc[5]), "f"(acc[6]), "f"(acc[7])
                     : "memory");
        if (hl == 0) atomicAdd(&g_cnts[g], 1.0f);
    } else {
        __half2 h0 = __floats2half2_rn(acc[0], acc[1]);
        __half2 h1 = __floats2half2_rn(acc[2], acc[3]);
        __half2 h2 = __floats2half2_rn(acc[4], acc[5]);
        __half2 h3 = __floats2half2_rn(acc[6], acc[7]);
        uint4 u;
        u.x = *(unsigned*)&h0; u.y = *(unsigned*)&h1;
        u.z = *(unsigned*)&h2; u.w = *(unsigned*)&h3;
        ((uint4*)g_A16)[(size_t)node * 16 + hl] = u;
    }
}

// ---------------- final linear ----------------------------------------------
__global__ void final_kernel(const float* __restrict__ Wl,
                             const float* __restrict__ bl,
                             float* __restrict__ out) {
    int g = blockIdx.x;
    int c = threadIdx.x;
    if (c >= N_CLASSES) return;
    float cnt = g_cnts[g];
    float inv = 1.0f / fmaxf(cnt, 1.0f);
    float acc = bl[c];
    for (int k = 0; k < FDIM; k++)
        acc += (g_sums[g * FDIM + k] * inv) * Wl[k * N_CLASSES + c];
    out[g * N_CLASSES + c] = acc;
}

// ---------------- launch ----------------------------------------------------
extern "C" void kernel_launch(void* const* d_in, const int* in_sizes, int n_in,
                              void* d_out, int out_size) {
    const float* x   = (const float*)d_in[0];
    const int*   ei  = (const int*)d_in[1];
    const int*   bat = (const int*)d_in[2];
    const float* W1  = (const float*)d_in[3];
    const float* b1  = (const float*)d_in[4];
    const float* W2  = (const float*)d_in[5];
    const float* b2  = (const float*)d_in[6];
    const float* W3  = (const float*)d_in[7];
    const float* b3  = (const float*)d_in[8];
    const float* Wl  = (const float*)d_in[9];
    const float* bl  = (const float*)d_in[10];
    float* out = (float*)d_out;

    const int* row = ei;
    const int* col = ei + N_EDGES;

    static cudaStream_t s1 = nullptr;
    static cudaEvent_t  ev_fork = nullptr, ev_join = nullptr;
    if (!s1) {
        cudaFuncSetAttribute(gemm_wmma_kernel,
                             cudaFuncAttributeMaxDynamicSharedMemorySize,
                             GEMM_SMEM_BYTES);
        cudaStreamCreateWithFlags(&s1, cudaStreamNonBlocking);
        cudaEventCreateWithFlags(&ev_fork, cudaEventDisableTiming);
        cudaEventCreateWithFlags(&ev_join, cudaEventDisableTiming);
    }

    const int gemm_blocks = N_NODES / GEMM_BM;              // 625
    const int gather_blocks = (N_NODES / 2 + 7) / 8;        // 2 nodes/warp

    __half* X16; cudaGetSymbolAddress((void**)&X16, g_X16);
    __half* A16; cudaGetSymbolAddress((void**)&A16, g_A16);
    __half* B16; cudaGetSymbolAddress((void**)&B16, g_B16);
    __half* Whi; cudaGetSymbolAddress((void**)&Whi, g_Whi);
    __half* Wlo; cudaGetSymbolAddress((void**)&Wlo, g_Wlo);

    // fork: CSR build on side stream, overlapped with conversions + gemm1
    cudaEventRecord(ev_fork, 0);
    cudaStreamWaitEvent(s1, ev_fork, 0);

    init_kernel<<<(N_NODES + 255) / 256, 256, 0, s1>>>();
    deg_count_kernel<<<(N_EDGES + 255) / 256, 256, 0, s1>>>(col);
    scan_fused_kernel<<<SCAN_NB, SCAN_B, 0, s1>>>();
    fill_kernel<<<(N_EDGES + 255) / 256, 256, 0, s1>>>(row, col);
    cudaEventRecord(ev_join, s1);

    // main stream
    x_to_h_kernel<<<(N_NODES * 32 + 255) / 256, 256>>>(x);
    w_split_kernel<<<(FDIM * FDIM + 255) / 256, 256>>>(W1, W2, W3);
    gemm_wmma_kernel<<<gemm_blocks, 256, GEMM_SMEM_BYTES>>>(X16, Whi, Wlo, B16);
    cudaStreamWaitEvent(0, ev_join, 0);

    gather_kernel<0><<<gather_blocks, 256>>>(b1, bat);
    gemm_wmma_kernel<<<gemm_blocks, 256, GEMM_SMEM_BYTES>>>(
        A16, Whi + FDIM * FDIM, Wlo + FDIM * FDIM, B16);
    gather_kernel<0><<<gather_blocks, 256>>>(b2, bat);
    gemm_wmma_kernel<<<gemm_blocks, 256, GEMM_SMEM_BYTES>>>(
        A16, Whi + 2 * FDIM * FDIM, Wlo + 2 * FDIM * FDIM, B16);
    gather_kernel<1><<<gather_blocks, 256>>>(b3, bat);

    final_kernel<<<N_GRAPHS, 32>>>(Wl, bl, out);
}

// round 10
// speedup vs baseline: 1.0642x; 1.0642x over previous
#include <cuda_runtime.h>
#include <cuda_fp16.h>
#include <mma.h>
#include <math.h>

using namespace nvcuda;

#define N_NODES   40000
#define N_EDGES   640000
#define FDIM      128
#define N_GRAPHS  64
#define N_CLASSES 10

#define SCAN_B    1024
#define SCAN_NB   ((N_NODES + SCAN_B - 1) / SCAN_B)   // 40

// ---------------- scratch (device globals; no allocations) ------------------
__device__ __align__(16) __half g_A16[N_NODES * FDIM];
__device__ __align__(16) __half g_B16[N_NODES * FDIM];
__device__ int    g_indeg[N_NODES];
__device__ float  g_dis[N_NODES];
__device__ int    g_off[N_NODES];
__device__ int    g_cursor[N_NODES];
__device__ int    g_bsum[SCAN_NB];
__device__ int2   g_srcwt[N_EDGES];
__device__ float  g_sums[N_GRAPHS * FDIM];
__device__ float  g_cnts[N_GRAPHS];

// ---------------- degree ----------------------------------------------------
__global__ void deg_init_kernel() {
    int i = blockIdx.x * blockDim.x + threadIdx.x;
    if (i < N_NODES) g_indeg[i] = 0;
}

__global__ void deg_count_kernel(const int* __restrict__ col) {
    int e = blockIdx.x * blockDim.x + threadIdx.x;
    if (e < N_EDGES) atomicAdd(&g_indeg[col[e]], 1);
}

// ---------------- scan (dis fused into pass A) --------------------------------
__global__ void scanA_kernel() {
    __shared__ int s[SCAN_B];
    int tid = threadIdx.x;
    int gid = blockIdx.x * SCAN_B + tid;
    int v = (gid < N_NODES) ? g_indeg[gid] : 0;
    if (gid < N_NODES) g_dis[gid] = rsqrtf((float)(v + 1));
    s[tid] = v;
    __syncthreads();
#pragma unroll
    for (int off = 1; off < SCAN_B; off <<= 1) {
        int t = 0;
        if (tid >= off) t = s[tid - off];
        __syncthreads();
        if (tid >= off) s[tid] += t;
        __syncthreads();
    }
    if (gid < N_NODES) g_off[gid] = s[tid] - v;
    if (tid == SCAN_B - 1) g_bsum[blockIdx.x] = s[tid];
}

__global__ void scanB_kernel() {
    if (threadIdx.x == 0) {
        int run = 0;
        for (int i = 0; i < SCAN_NB; i++) {
            int t = g_bsum[i];
            g_bsum[i] = run;
            run += t;
        }
    }
}

__global__ void scanC_kernel() {
    int gid = blockIdx.x * SCAN_B + threadIdx.x;
    if (gid < N_NODES) {
        int o = g_off[gid] + g_bsum[blockIdx.x];
        g_off[gid] = o;
        g_cursor[gid] = o;
    }
}

// ---------------- CSR fill ---------------------------------------------------
__global__ void fill_kernel(const int* __restrict__ row,
                            const int* __restrict__ col) {
    int e = blockIdx.x * blockDim.x + threadIdx.x;
    if (e >= N_EDGES) return;
    int r = row[e];
    int c = col[e];
    int p = atomicAdd(&g_cursor[c], 1);
    float w = g_dis[r] * g_dis[c];
    g_srcwt[p] = make_int2(r, __float_as_int(w));
}

// ---------------- wmma GEMM: Y16 = X @ W  (fp32 W, inline hi/lo split) -------
// XF32: layer-1 reads fp32 node features and converts while staging.
#define GEMM_BM  64
#define LDP      136
#define GEMM_SMEM_BYTES ((2 * 128 * LDP + GEMM_BM * LDP) * 2)
template <bool XF32>
__global__ __launch_bounds__(256, 2)
void gemm_wmma_kernel(const void* __restrict__ Xv,
                      const float* __restrict__ W,
                      __half* __restrict__ Y) {
    extern __shared__ __half smh[];
    __half* Wh = smh;                    // 128 x LDP (hi)
    __half* Wl = smh + 128 * LDP;        // 128 x LDP (lo residual)
    __half* Xs = smh + 2 * 128 * LDP;    // 64  x LDP

    int tid  = threadIdx.x;
    int row0 = blockIdx.x * GEMM_BM;

    // stage W with inline Markidis split: 4096 float4 of fp32 (W hot in L2)
    const float4* W4 = (const float4*)W;
#pragma unroll
    for (int i = 0; i < 16; i++) {
        int idx = tid + 256 * i;             // float4 index; 32 per row
        float4 w = W4[idx];
        int r = idx >> 5, c = (idx & 31) * 4;
        __half h0 = __float2half_rn(w.x);
        __half h1 = __float2half_rn(w.y);
        __half h2 = __float2half_rn(w.z);
        __half h3 = __float2half_rn(w.w);
        __half l0 = __float2half_rn(w.x - __half2float(h0));
        __half l1 = __float2half_rn(w.y - __half2float(h1));
        __half l2 = __float2half_rn(w.z - __half2float(h2));
        __half l3 = __float2half_rn(w.w - __half2float(h3));
        __half2 hh0 = __halves2half2(h0, h1);
        __half2 hh1 = __halves2half2(h2, h3);
        __half2 ll0 = __halves2half2(l0, l1);
        __half2 ll1 = __halves2half2(l2, l3);
        uint2 uh; uh.x = *(unsigned*)&hh0; uh.y = *(unsigned*)&hh1;
        uint2 ul; ul.x = *(unsigned*)&ll0; ul.y = *(unsigned*)&ll1;
        *(uint2*)(Wh + r * LDP + c) = uh;
        *(uint2*)(Wl + r * LDP + c) = ul;
    }

    // stage X tile
    if (XF32) {
        const float4* X4 = (const float4*)((const float*)Xv + (size_t)row0 * FDIM);
#pragma unroll
        for (int i = 0; i < 8; i++) {
            int idx = tid + 256 * i;             // float4 idx; 32 per row
            float4 v = X4[idx];
            int r = idx >> 5, c = (idx & 31) * 4;
            __half2 h0 = __floats2half2_rn(v.x, v.y);
            __half2 h1 = __floats2half2_rn(v.z, v.w);
            uint2 u; u.x = *(unsigned*)&h0; u.y = *(unsigned*)&h1;
            *(uint2*)(Xs + r * LDP + c) = u;
        }
    } else {
        const float4* X4 = (const float4*)((const __half*)Xv + (size_t)row0 * FDIM);
#pragma unroll
        for (int i = 0; i < 4; i++) {
            int idx = tid + 256 * i;             // float4 = 8 halves; 16 per row
            int r = idx >> 4, c8 = idx & 15;
            *(float4*)(Xs + r * LDP + c8 * 8) = X4[idx];
        }
    }
    __syncthreads();

    int warp = tid >> 5;
    int wr = warp >> 1;
    int wc = warp & 1;

    wmma::fragment<wmma::matrix_a, 16, 16, 16, __half, wmma::row_major> a_frag;
    wmma::fragment<wmma::matrix_b, 16, 16, 16, __half, wmma::row_major> bh, bl;
    wmma::fragment<wmma::accumulator, 16, 16, 16, float> acc[4];
#pragma unroll
    for (int j = 0; j < 4; j++) wmma::fill_fragment(acc[j], 0.0f);

#pragma unroll
    for (int kk = 0; kk < 8; kk++) {
        wmma::load_matrix_sync(a_frag, Xs + (wr * 16) * LDP + kk * 16, LDP);
#pragma unroll
        for (int j = 0; j < 4; j++) {
            int coff = wc * 64 + j * 16;
            wmma::load_matrix_sync(bh, Wh + (kk * 16) * LDP + coff, LDP);
            wmma::mma_sync(acc[j], a_frag, bh, acc[j]);
            wmma::load_matrix_sync(bl, Wl + (kk * 16) * LDP + coff, LDP);
            wmma::mma_sync(acc[j], a_frag, bl, acc[j]);
        }
    }

#pragma unroll
    for (int j = 0; j < 4; j++) {
        wmma::fragment<wmma::accumulator, 16, 16, 16, __half> hfrag;
#pragma unroll
        for (int t = 0; t < hfrag.num_elements; t++)
            hfrag.x[t] = __float2half_rn(acc[j].x[t]);
        wmma::store_matrix_sync(
            Y + (size_t)(row0 + wr * 16) * FDIM + wc * 64 + j * 16,
            hfrag, FDIM, wmma::mem_row_major);
    }
}

// ---------------- fp16 quad -> float4 ---------------------------------------
__device__ __forceinline__ float4 h4_to_f4(uint2 u) {
    __half2 a = *(__half2*)&u.x;
    __half2 b = *(__half2*)&u.y;
    float2 fa = __half22float2(a);
    float2 fb = __half22float2(b);
    return make_float4(fa.x, fa.y, fb.x, fb.y);
}

__device__ __forceinline__ void edge_fma(float4& acc, int src, float w,
                                         const uint2* B2, int lane) {
    float4 v = h4_to_f4(__ldg(&B2[(size_t)src * 32 + lane]));
    acc.x = fmaf(w, v.x, acc.x);
    acc.y = fmaf(w, v.y, acc.y);
    acc.z = fmaf(w, v.z, acc.z);
    acc.w = fmaf(w, v.w, acc.w);
}

// ---------------- CSR gather (R7-proven: warp/node, 4-way unroll) ------------
template <int POOL>
__global__ void gather_kernel(const float* __restrict__ bias,
                              const int* __restrict__ batch) {
    int node = blockIdx.x * (blockDim.x >> 5) + (threadIdx.x >> 5);
    if (node >= N_NODES) return;
    int lane = threadIdx.x & 31;

    const uint2* B2 = (const uint2*)g_B16;

    int beg = g_off[node];
    int deg = g_indeg[node];

    float dn = g_dis[node];
    float sl = dn * dn;
    float4 sv = h4_to_f4(B2[(size_t)node * 32 + lane]);
    float4 acc = make_float4(sv.x * sl, sv.y * sl, sv.z * sl, sv.w * sl);

    for (int base = 0; base < deg; base += 32) {
        int rem = deg - base; if (rem > 32) rem = 32;
        int2 my = make_int2(0, 0);
        if (lane < rem) my = __ldg(&g_srcwt[beg + base + lane]);

        int j = 0;
        for (; j + 4 <= rem; j += 4) {
            int   s0 = __shfl_sync(0xffffffffu, my.x, j);
            int   s1 = __shfl_sync(0xffffffffu, my.x, j + 1);
            int   s2 = __shfl_sync(0xffffffffu, my.x, j + 2);
            int   s3 = __shfl_sync(0xffffffffu, my.x, j + 3);
            float w0 = __int_as_float(__shfl_sync(0xffffffffu, my.y, j));
            float w1 = __int_as_float(__shfl_sync(0xffffffffu, my.y, j + 1));
            float w2 = __int_as_float(__shfl_sync(0xffffffffu, my.y, j + 2));
            float w3 = __int_as_float(__shfl_sync(0xffffffffu, my.y, j + 3));
            float4 v0 = h4_to_f4(__ldg(&B2[(size_t)s0 * 32 + lane]));
            float4 v1 = h4_to_f4(__ldg(&B2[(size_t)s1 * 32 + lane]));
            float4 v2 = h4_to_f4(__ldg(&B2[(size_t)s2 * 32 + lane]));
            float4 v3 = h4_to_f4(__ldg(&B2[(size_t)s3 * 32 + lane]));
            acc.x = fmaf(w0, v0.x, acc.x); acc.y = fmaf(w0, v0.y, acc.y);
            acc.z = fmaf(w0, v0.z, acc.z); acc.w = fmaf(w0, v0.w, acc.w);
            acc.x = fmaf(w1, v1.x, acc.x); acc.y = fmaf(w1, v1.y, acc.y);
            acc.z = fmaf(w1, v1.z, acc.z); acc.w = fmaf(w1, v1.w, acc.w);
            acc.x = fmaf(w2, v2.x, acc.x); acc.y = fmaf(w2, v2.y, acc.y);
            acc.z = fmaf(w2, v2.z, acc.z); acc.w = fmaf(w2, v2.w, acc.w);
            acc.x = fmaf(w3, v3.x, acc.x); acc.y = fmaf(w3, v3.y, acc.y);
            acc.z = fmaf(w3, v3.z, acc.z); acc.w = fmaf(w3, v3.w, acc.w);
        }
        for (; j < rem; j++) {
            int   s = __shfl_sync(0xffffffffu, my.x, j);
            float w = __int_as_float(__shfl_sync(0xffffffffu, my.y, j));
            edge_fma(acc, s, w, B2, lane);
        }
    }

    float4 bv = __ldg(&((const float4*)bias)[lane]);
    acc.x = fmaxf(acc.x + bv.x, 0.f);
    acc.y = fmaxf(acc.y + bv.y, 0.f);
    acc.z = fmaxf(acc.z + bv.z, 0.f);
    acc.w = fmaxf(acc.w + bv.w, 0.f);

    if (POOL) {
        int g = __ldg(&batch[node]);
        float* dst = g_sums + (size_t)g * FDIM + lane * 4;
        asm volatile("red.global.add.v4.f32 [%0], {%1, %2, %3, %4};"
                     :: "l"(dst), "f"(acc.x), "f"(acc.y), "f"(acc.z), "f"(acc.w)
                     : "memory");
        if (lane == 0) atomicAdd(&g_cnts[g], 1.0f);
    } else {
        __half2 h0 = __floats2half2_rn(acc.x, acc.y);
        __half2 h1 = __floats2half2_rn(acc.z, acc.w);
        uint2 u; u.x = *(unsigned*)&h0; u.y = *(unsigned*)&h1;
        ((uint2*)g_A16)[(size_t)node * 32 + lane] = u;
    }
}

// ---------------- pooling ----------------------------------------------------
__global__ void zero_pool_kernel() {
    int i = threadIdx.x;
    for (int k = i; k < N_GRAPHS * FDIM; k += blockDim.x) g_sums[k] = 0.f;
    if (i < N_GRAPHS) g_cnts[i] = 0.f;
}

// ---------------- final linear ----------------------------------------------
__global__ void final_kernel(const float* __restrict__ Wl,
                             const float* __restrict__ bl,
                             float* __restrict__ out) {
    int g = blockIdx.x;
    int c = threadIdx.x;
    if (c >= N_CLASSES) return;
    float cnt = g_cnts[g];
    float inv = 1.0f / fmaxf(cnt, 1.0f);
    float acc = bl[c];
    for (int k = 0; k < FDIM; k++)
        acc += (g_sums[g * FDIM + k] * inv) * Wl[k * N_CLASSES + c];
    out[g * N_CLASSES + c] = acc;
}

// ---------------- launch ----------------------------------------------------
extern "C" void kernel_launch(void* const* d_in, const int* in_sizes, int n_in,
                              void* d_out, int out_size) {
    const float* x   = (const float*)d_in[0];
    const int*   ei  = (const int*)d_in[1];
    const int*   bat = (const int*)d_in[2];
    const float* W1  = (const float*)d_in[3];
    const float* b1  = (const float*)d_in[4];
    const float* W2  = (const float*)d_in[5];
    const float* b2  = (const float*)d_in[6];
    const float* W3  = (const float*)d_in[7];
    const float* b3  = (const float*)d_in[8];
    const float* Wl  = (const float*)d_in[9];
    const float* bl  = (const float*)d_in[10];
    float* out = (float*)d_out;

    const int* row = ei;
    const int* col = ei + N_EDGES;

    static cudaStream_t s1 = nullptr;
    static cudaEvent_t  ev_fork = nullptr, ev_join = nullptr;
    if (!s1) {
        cudaFuncSetAttribute(gemm_wmma_kernel<true>,
                             cudaFuncAttributeMaxDynamicSharedMemorySize,
                             GEMM_SMEM_BYTES);
        cudaFuncSetAttribute(gemm_wmma_kernel<false>,
                             cudaFuncAttributeMaxDynamicSharedMemorySize,
                             GEMM_SMEM_BYTES);
        cudaStreamCreateWithFlags(&s1, cudaStreamNonBlocking);
        cudaEventCreateWithFlags(&ev_fork, cudaEventDisableTiming);
        cudaEventCreateWithFlags(&ev_join, cudaEventDisableTiming);
    }

    const int gemm_blocks = N_NODES / GEMM_BM;          // 625
    const int node_warp_blocks = (N_NODES + 7) / 8;

    __half* A16; cudaGetSymbolAddress((void**)&A16, g_A16);
    __half* B16; cudaGetSymbolAddress((void**)&B16, g_B16);

    // fork: CSR build on side stream, overlapped with gemm1
    cudaEventRecord(ev_fork, 0);
    cudaStreamWaitEvent(s1, ev_fork, 0);

    deg_init_kernel<<<(N_NODES + 255) / 256, 256, 0, s1>>>();
    deg_count_kernel<<<(N_EDGES + 255) / 256, 256, 0, s1>>>(col);
    scanA_kernel<<<SCAN_NB, SCAN_B, 0, s1>>>();
    scanB_kernel<<<1, 32, 0, s1>>>();
    scanC_kernel<<<SCAN_NB, SCAN_B, 0, s1>>>();
    fill_kernel<<<(N_EDGES + 255) / 256, 256, 0, s1>>>(row, col);
    zero_pool_kernel<<<1, 256, 0, s1>>>();
    cudaEventRecord(ev_join, s1);

    // main stream: layer-1 GEMM reads fp32 x directly (no conversion pass)
    gemm_wmma_kernel<true><<<gemm_blocks, 256, GEMM_SMEM_BYTES>>>(x, W1, B16);
    cudaStreamWaitEvent(0, ev_join, 0);

    gather_kernel<0><<<node_warp_blocks, 256>>>(b1, bat);
    gemm_wmma_kernel<false><<<gemm_blocks, 256, GEMM_SMEM_BYTES>>>(A16, W2, B16);
    gather_kernel<0><<<node_warp_blocks, 256>>>(b2, bat);
    gemm_wmma_kernel<false><<<gemm_blocks, 256, GEMM_SMEM_BYTES>>>(A16, W3, B16);
    gather_kernel<1><<<node_warp_blocks, 256>>>(b3, bat);

    final_kernel<<<N_GRAPHS, 32>>>(Wl, bl, out);
}